// round 8
// baseline (speedup 1.0000x reference)
#include <cuda_runtime.h>
#include <cuda_fp16.h>
#include <math.h>
#include <stdint.h>

#define NT 128
#define BUF 8192                       // one 64x64 fp16 buffer: 64 rows x 128B
#define STAGE_OFF (6*BUF)              // fp32 staging 32x36 (padded)
#define STAGE_STR 36
#define RED_OFF (STAGE_OFF + 32*STAGE_STR*4)
#define SMEM_TOTAL (RED_OFF + 64)
// buffer roles: 0,1 = Y splits ; 2,3 = Z splits ; 4,5 = T/A splits

__device__ __forceinline__ uint32_t swz(uint32_t b) { return b ^ ((b >> 3) & 0x70); }

__device__ __forceinline__ uint32_t smem_u32(const void* p) {
    uint32_t a;
    asm("{ .reg .u64 t; cvta.to.shared.u64 t, %1; cvt.u32.u64 %0, t; }" : "=r"(a) : "l"(p));
    return a;
}

__device__ __forceinline__ void ldsm4(uint32_t* r, uint32_t addr) {
    asm volatile("ldmatrix.sync.aligned.m8n8.x4.shared.b16 {%0,%1,%2,%3}, [%4];"
                 : "=r"(r[0]), "=r"(r[1]), "=r"(r[2]), "=r"(r[3]) : "r"(addr));
}

__device__ __forceinline__ uint32_t movm(uint32_t s) {
    uint32_t d;
    asm volatile("movmatrix.sync.aligned.m8n8.trans.b16 %0, %1;" : "=r"(d) : "r"(s));
    return d;
}

__device__ __forceinline__ void mma16816(float* c, const uint32_t* a, const uint32_t* b) {
    asm volatile("mma.sync.aligned.m16n8k16.row.col.f32.f16.f16.f32 "
                 "{%0,%1,%2,%3}, {%4,%5,%6,%7}, {%8,%9}, {%0,%1,%2,%3};"
                 : "+f"(c[0]), "+f"(c[1]), "+f"(c[2]), "+f"(c[3])
                 : "r"(a[0]), "r"(a[1]), "r"(a[2]), "r"(a[3]), "r"(b[0]), "r"(b[1]));
}

// fp32 -> 2-term fp16 split
__device__ __forceinline__ void split2(float v, __half& h1, __half& h2) {
    h1 = __float2half_rn(v);
    h2 = __float2half_rn(v - __half2float(h1));
}
__device__ __forceinline__ uint32_t packh(__half a, __half b) {
    __half2 t; t.x = a; t.y = b;
    return *reinterpret_cast<uint32_t*>(&t);
}

// D = Ma @ Mb, both symmetric AND commuting (polynomials of SPD A) -> D symmetric.
// Tiles: role0 -> D00 full-k, role3 -> D11 full-k,
//        role1 -> D01 k-half0 (+merge+write D01 & D10^T), role2 -> D01 k-half1 (partial).
// Roles rotate with gemm index g so tensor work balances across SMSPs.
// MODE 0: dst = D   MODE 1: dst = 1.5I - 0.5 D   MODE 2: gmem O = scale*D
template <int MODE>
__device__ __forceinline__ void gemm64(uint32_t sbase, char* smem,
                                       int a1, int a2, int b1, int b2,
                                       int d1, int d2,
                                       float* __restrict__ O, float scale,
                                       int wid, int lane, int g)
{
    const int role = (wid + g) & 3;
    const int wm = (role == 3) ? 1 : 0;
    const int wn = (role == 0) ? 0 : 1;
    const int kbeg = (role == 2) ? 1 : 0;
    const int kend = (role == 1) ? 1 : 2;

    __syncthreads();   // operands from previous epilogue are visible

    float acc[2][4][4];
#pragma unroll
    for (int mt = 0; mt < 2; ++mt)
#pragma unroll
        for (int j = 0; j < 4; ++j)
#pragma unroll
            for (int q = 0; q < 4; ++q) acc[mt][j][q] = 0.0f;

    const int arow = wm * 32 + (lane & 15);
    const int acol = (lane >> 4) * 16;
    const int bl = lane & 7;
    const int bg = lane >> 3;
    const uint32_t bcol = (uint32_t)((bg >> 1) * 32 + (bg & 1) * 16);

#pragma unroll
    for (int ktp = 0; ktp < 2; ++ktp) {
        if (ktp < kbeg || ktp >= kend) continue;
        // ---- A fragments for this k-tile pair ----
        uint32_t A1[2][2][4], A2[2][2][4];
#pragma unroll
        for (int mt = 0; mt < 2; ++mt)
#pragma unroll
            for (int ktl = 0; ktl < 2; ++ktl) {
                uint32_t rel = swz((uint32_t)((arow + mt * 16) * 128 +
                                              ktp * 64 + ktl * 32 + acol));
                ldsm4(A1[mt][ktl], sbase + a1 + rel);
                ldsm4(A2[mt][ktl], sbase + a2 + rel);
            }
        // ---- B per n-tile ----
#pragma unroll
        for (int j = 0; j < 4; ++j) {
            const uint32_t rowb = (uint32_t)((wn * 32 + j * 8 + bl) * 128);
            uint32_t rel = swz(rowb + ktp * 64 + bcol);
            uint32_t Bx[4], Cx[4];
            ldsm4(Bx, sbase + b1 + rel);
            ldsm4(Cx, sbase + b2 + rel);
#pragma unroll
            for (int ktl = 0; ktl < 2; ++ktl) {
#pragma unroll
                for (int mt = 0; mt < 2; ++mt) {
                    mma16816(acc[mt][j], A1[mt][ktl], Bx + 2 * ktl);
                    mma16816(acc[mt][j], A1[mt][ktl], Cx + 2 * ktl);
                    mma16816(acc[mt][j], A2[mt][ktl], Bx + 2 * ktl);
                }
            }
        }
    }

    const int gr = lane >> 2, qp = lane & 3;

    // role2 stashes fp32 partials of D01 (k-half1)
    if (role == 2) {
        float* stg = (float*)(smem + STAGE_OFF);
#pragma unroll
        for (int mt = 0; mt < 2; ++mt)
#pragma unroll
        for (int j = 0; j < 4; ++j)
#pragma unroll
        for (int half = 0; half < 2; ++half) {
            int R = mt * 16 + half * 8 + gr;
            int C = j * 8 + 2 * qp;
            *(float2*)(stg + R * STAGE_STR + C) =
                make_float2(acc[mt][j][half*2], acc[mt][j][half*2+1]);
        }
    }

    __syncthreads();   // reads done before in-place writes; partials visible

    if (role == 2) return;

    // role1 merges the other k-half
    if (role == 1) {
        const float* stg = (const float*)(smem + STAGE_OFF);
#pragma unroll
        for (int mt = 0; mt < 2; ++mt)
#pragma unroll
        for (int j = 0; j < 4; ++j)
#pragma unroll
        for (int half = 0; half < 2; ++half) {
            int R = mt * 16 + half * 8 + gr;
            int C = j * 8 + 2 * qp;
            float2 p = *(const float2*)(stg + R * STAGE_STR + C);
            acc[mt][j][half*2]   += p.x;
            acc[mt][j][half*2+1] += p.y;
        }
    }

    // ---- transform in place ----
#pragma unroll
    for (int mt = 0; mt < 2; ++mt)
#pragma unroll
    for (int j = 0; j < 4; ++j)
#pragma unroll
    for (int half = 0; half < 2; ++half) {
        const int row  = wm * 32 + mt * 16 + half * 8 + gr;
        const int colb = wn * 32 + j * 8 + 2 * qp;
        float v0 = acc[mt][j][half*2], v1 = acc[mt][j][half*2+1];
        if (MODE == 1) {
            v0 = (colb     == row ? 1.5f : 0.0f) - 0.5f * v0;
            v1 = (colb + 1 == row ? 1.5f : 0.0f) - 0.5f * v1;
        }
        if (MODE == 2) { v0 *= scale; v1 *= scale; }
        acc[mt][j][half*2] = v0; acc[mt][j][half*2+1] = v1;
    }

    // ---- store own tile ----
#pragma unroll
    for (int mt = 0; mt < 2; ++mt)
#pragma unroll
    for (int j = 0; j < 4; ++j)
#pragma unroll
    for (int half = 0; half < 2; ++half) {
        const int row  = wm * 32 + mt * 16 + half * 8 + gr;
        const int colb = wn * 32 + j * 8 + 2 * qp;
        float v0 = acc[mt][j][half*2], v1 = acc[mt][j][half*2+1];
        if (MODE == 2) {
            *(float2*)(O + row * 64 + colb) = make_float2(v0, v1);
        } else {
            __half p0, q0, p1, q1;
            split2(v0, p0, q0);
            split2(v1, p1, q1);
            uint32_t off = swz((uint32_t)(row * 128 + colb * 2));
            *(uint32_t*)(smem + d1 + off) = packh(p0, p1);
            *(uint32_t*)(smem + d2 + off) = packh(q0, q1);
        }
    }

    // ---- role1: write D10 = D01^T via movmatrix register transpose ----
    if (role == 1) {
#pragma unroll
        for (int mt = 0; mt < 2; ++mt)
#pragma unroll
        for (int j = 0; j < 4; ++j)
#pragma unroll
        for (int half = 0; half < 2; ++half) {
            uint32_t u0 = __float_as_uint(acc[mt][j][half*2]);
            uint32_t u1 = __float_as_uint(acc[mt][j][half*2+1]);
            uint32_t lo = __byte_perm(u0, u1, 0x5410);
            uint32_t hi = __byte_perm(u0, u1, 0x7632);
            uint32_t lot = movm(lo);
            uint32_t hit = movm(hi);
            float w0 = __uint_as_float(__byte_perm(lot, hit, 0x5410));
            float w1 = __uint_as_float(__byte_perm(lot, hit, 0x7632));
            const int row  = 32 + j * 8 + gr;             // transposed block coords
            const int colb = mt * 16 + half * 8 + 2 * qp;
            if (MODE == 2) {
                *(float2*)(O + row * 64 + colb) = make_float2(w0, w1);
            } else {
                __half p0, q0, p1, q1;
                split2(w0, p0, q0);
                split2(w1, p1, q1);
                uint32_t off = swz((uint32_t)(row * 128 + colb * 2));
                *(uint32_t*)(smem + d1 + off) = packh(p0, p1);
                *(uint32_t*)(smem + d2 + off) = packh(q0, q1);
            }
        }
    }
}

__global__ void __launch_bounds__(NT, 4)
isqrtm_hmma_kernel(const float* __restrict__ x, float* __restrict__ out)
{
    extern __shared__ char smem[];
    const uint32_t sbase = smem_u32(smem);
    float* red = (float*)(smem + RED_OFF);

    const int tid = threadIdx.x;
    const int wid = tid >> 5, lane = tid & 31;
    const int b = blockIdx.x;
    const float* X = x + (size_t)b * 4096;
    float* O = out + (size_t)b * 4096;

    // ---- trace(X) ----
    float tr = (tid < 64) ? __ldg(X + tid * 65) : 0.0f;
#pragma unroll
    for (int o = 16; o; o >>= 1) tr += __shfl_xor_sync(0xFFFFFFFFu, tr, o);
    if (lane == 0) red[wid] = tr;
    __syncthreads();
    const float normA = red[0] + red[1];
    const float inv = 1.0f / normA;
    const float sq  = sqrtf(normA);
    __syncthreads();

    // ---- prologue: A = X/normA -> bufs 4,5 ; Z = 1.5I - 0.5A -> bufs 2,3 ----
    {
        const int r  = tid >> 1;
        const int c0 = (tid & 1) * 32;
#pragma unroll
        for (int q = 0; q < 16; ++q) {
            const int c = c0 + 2 * q;
            float2 f = *(const float2*)(X + r * 64 + c);
            float a0 = f.x * inv, a1 = f.y * inv;
            float z0 = (c     == r ? 1.5f : 0.0f) - 0.5f * a0;
            float z1 = (c + 1 == r ? 1.5f : 0.0f) - 0.5f * a1;
            __half p0, s0, p1, s1;
            uint32_t off = swz((uint32_t)(r * 128 + c * 2));
            split2(a0, p0, s0); split2(a1, p1, s1);
            *(uint32_t*)(smem + 4 * BUF + off) = packh(p0, p1);
            *(uint32_t*)(smem + 5 * BUF + off) = packh(s0, s1);
            split2(z0, p0, s0); split2(z1, p1, s1);
            *(uint32_t*)(smem + 2 * BUF + off) = packh(p0, p1);
            *(uint32_t*)(smem + 3 * BUF + off) = packh(s0, s1);
        }
    }

    // ---- Newton-Schulz chain (12 GEMMs) ----
    // Y = A @ Z
    gemm64<0>(sbase, smem, 4*BUF, 5*BUF, 2*BUF, 3*BUF, 0*BUF, 1*BUF, O, 0.f, wid, lane, 0);
#pragma unroll 1
    for (int it = 0; it < 3; ++it) {
        const int g = 1 + it * 3;
        // T = 1.5I - 0.5 * Z@Y
        gemm64<1>(sbase, smem, 2*BUF, 3*BUF, 0*BUF, 1*BUF, 4*BUF, 5*BUF, O, 0.f, wid, lane, g);
        // Y = Y @ T
        gemm64<0>(sbase, smem, 0*BUF, 1*BUF, 4*BUF, 5*BUF, 0*BUF, 1*BUF, O, 0.f, wid, lane, g + 1);
        // Z = T @ Z
        gemm64<0>(sbase, smem, 4*BUF, 5*BUF, 2*BUF, 3*BUF, 2*BUF, 3*BUF, O, 0.f, wid, lane, g + 2);
    }
    // T = 1.5I - 0.5 * Z@Y ; out = sqrt(normA) * (Y @ T)
    gemm64<1>(sbase, smem, 2*BUF, 3*BUF, 0*BUF, 1*BUF, 4*BUF, 5*BUF, O, 0.f, wid, lane, 10);
    gemm64<2>(sbase, smem, 0*BUF, 1*BUF, 4*BUF, 5*BUF, 0, 0, O, sq, wid, lane, 11);
}

extern "C" void kernel_launch(void* const* d_in, const int* in_sizes, int n_in,
                              void* d_out, int out_size)
{
    const float* x = (const float*)d_in[0];
    float* out = (float*)d_out;
    const int batches = in_sizes[0] / 4096;

    cudaFuncSetAttribute(isqrtm_hmma_kernel,
                         cudaFuncAttributeMaxDynamicSharedMemorySize, SMEM_TOTAL);
    isqrtm_hmma_kernel<<<batches, NT, SMEM_TOTAL>>>(x, out);
}

// round 10
// speedup vs baseline: 1.0384x; 1.0384x over previous
#include <cuda_runtime.h>
#include <cuda_fp16.h>
#include <math.h>
#include <stdint.h>

#define NT 128
#define BUF 8192                       // one 64x64 fp16 buffer: 64 rows x 128B
#define M1OFF (6*BUF)                  // second matrix's buffer block
#define RED_OFF (12*BUF)
#define SMEM_TOTAL (RED_OFF + 64)
// per-matrix buffer roles: 0,1 = Y splits ; 2,3 = Z splits ; 4,5 = T/A splits

__device__ __forceinline__ uint32_t swz(uint32_t b) { return b ^ ((b >> 3) & 0x70); }

__device__ __forceinline__ uint32_t smem_u32(const void* p) {
    uint32_t a;
    asm("{ .reg .u64 t; cvta.to.shared.u64 t, %1; cvt.u32.u64 %0, t; }" : "=r"(a) : "l"(p));
    return a;
}

__device__ __forceinline__ void ldsm4(uint32_t* r, uint32_t addr) {
    asm volatile("ldmatrix.sync.aligned.m8n8.x4.shared.b16 {%0,%1,%2,%3}, [%4];"
                 : "=r"(r[0]), "=r"(r[1]), "=r"(r[2]), "=r"(r[3]) : "r"(addr));
}

__device__ __forceinline__ void mma16816(float* c, const uint32_t* a,
                                         uint32_t b0, uint32_t b1) {
    asm volatile("mma.sync.aligned.m16n8k16.row.col.f32.f16.f16.f32 "
                 "{%0,%1,%2,%3}, {%4,%5,%6,%7}, {%8,%9}, {%0,%1,%2,%3};"
                 : "+f"(c[0]), "+f"(c[1]), "+f"(c[2]), "+f"(c[3])
                 : "r"(a[0]), "r"(a[1]), "r"(a[2]), "r"(a[3]), "r"(b0), "r"(b1));
}

// fp32 -> 2-term fp16 split
__device__ __forceinline__ void split2(float v, __half& h1, __half& h2) {
    h1 = __float2half_rn(v);
    h2 = __float2half_rn(v - __half2float(h1));
}
__device__ __forceinline__ uint32_t packh(__half a, __half b) {
    __half2 t; t.x = a; t.y = b;
    return *reinterpret_cast<uint32_t*>(&t);
}

// ---- load + MMA phase: acc = (a1+a2) @ (b1+b2), 3 partial products ----
// Both operands symmetric -> row.col is transpose-free. No barriers inside.
__device__ __forceinline__ void mma_phase(uint32_t sbase,
                                          int a1, int a2, int b1, int b2,
                                          int wm, int wn, int lane,
                                          float acc[2][4][4])
{
#pragma unroll
    for (int mt = 0; mt < 2; ++mt)
#pragma unroll
        for (int j = 0; j < 4; ++j)
#pragma unroll
            for (int q = 0; q < 4; ++q) acc[mt][j][q] = 0.0f;

    const int arow = wm * 32 + (lane & 15);
    const int acol = (lane >> 4) * 16;
    const int bl = lane & 7;
    const int bg = lane >> 3;
    const uint32_t bcol = (uint32_t)((bg >> 1) * 32 + (bg & 1) * 16);

#pragma unroll
    for (int ktp = 0; ktp < 2; ++ktp) {
        uint32_t A1[2][2][4], A2[2][2][4];
#pragma unroll
        for (int mt = 0; mt < 2; ++mt)
#pragma unroll
            for (int ktl = 0; ktl < 2; ++ktl) {
                uint32_t rel = swz((uint32_t)((arow + mt * 16) * 128 +
                                              ktp * 64 + ktl * 32 + acol));
                ldsm4(A1[mt][ktl], sbase + a1 + rel);
                ldsm4(A2[mt][ktl], sbase + a2 + rel);
            }
#pragma unroll
        for (int j = 0; j < 4; ++j) {
            const uint32_t rowb = (uint32_t)((wn * 32 + j * 8 + bl) * 128);
            uint32_t rel = swz(rowb + ktp * 64 + bcol);
            uint32_t Bx[4], Cx[4];
            ldsm4(Bx, sbase + b1 + rel);   // regs 0,1 = kt_lo ; 2,3 = kt_hi
            ldsm4(Cx, sbase + b2 + rel);
#pragma unroll
            for (int ktl = 0; ktl < 2; ++ktl) {
#pragma unroll
                for (int mt = 0; mt < 2; ++mt) {
                    mma16816(acc[mt][j], A1[mt][ktl], Bx[2*ktl], Bx[2*ktl+1]);
                    mma16816(acc[mt][j], A1[mt][ktl], Cx[2*ktl], Cx[2*ktl+1]);
                    mma16816(acc[mt][j], A2[mt][ktl], Bx[2*ktl], Bx[2*ktl+1]);
                }
            }
        }
    }
}

// ---- epilogue: transform, split, store. No barriers inside. ----
// MODE 0: dst = D   MODE 1: dst = 1.5I - 0.5 D   MODE 2: gmem O = scale*D
template <int MODE>
__device__ __forceinline__ void epi_phase(char* smem, int d1, int d2,
                                          float* __restrict__ O, float scale,
                                          int wm, int wn, int lane,
                                          const float acc[2][4][4])
{
    const int gr = lane >> 2, qp = lane & 3;
#pragma unroll
    for (int mt = 0; mt < 2; ++mt)
#pragma unroll
    for (int j = 0; j < 4; ++j) {
        const int colb = wn * 32 + j * 8 + 2 * qp;
#pragma unroll
        for (int half = 0; half < 2; ++half) {
            const int row = wm * 32 + mt * 16 + gr + half * 8;
            float v0 = acc[mt][j][half * 2 + 0];
            float v1 = acc[mt][j][half * 2 + 1];
            if (MODE == 1) {
                v0 = (colb     == row ? 1.5f : 0.0f) - 0.5f * v0;
                v1 = (colb + 1 == row ? 1.5f : 0.0f) - 0.5f * v1;
            }
            if (MODE == 2) {
                *(float2*)(O + row * 64 + colb) = make_float2(v0 * scale, v1 * scale);
            } else {
                __half p0, q0, p1, q1;
                split2(v0, p0, q0);
                split2(v1, p1, q1);
                uint32_t off = swz((uint32_t)(row * 128 + colb * 2));
                *(uint32_t*)(smem + d1 + off) = packh(p0, p1);
                *(uint32_t*)(smem + d2 + off) = packh(q0, q1);
            }
        }
    }
}

// One Newton-Schulz step applied to BOTH matrices of this CTA.
// sync; mma(m0); mma(m1); sync; epi(m0); epi(m1)
template <int MODE>
__device__ __forceinline__ void step2(uint32_t sbase, char* smem,
                                      int a1, int a2, int b1, int b2,
                                      int d1, int d2,
                                      float* __restrict__ O0, float* __restrict__ O1,
                                      float sc0, float sc1,
                                      int wm, int wn, int lane)
{
    float acc0[2][4][4], acc1[2][4][4];
    __syncthreads();   // previous epilogue writes visible
    mma_phase(sbase, a1, a2, b1, b2, wm, wn, lane, acc0);
    mma_phase(sbase, a1 + M1OFF, a2 + M1OFF, b1 + M1OFF, b2 + M1OFF,
              wm, wn, lane, acc1);
    __syncthreads();   // all reads done before in-place writes
    epi_phase<MODE>(smem, d1, d2, O0, sc0, wm, wn, lane, acc0);
    epi_phase<MODE>(smem, d1 + M1OFF, d2 + M1OFF, O1, sc1, wm, wn, lane, acc1);
}

__global__ void __launch_bounds__(NT, 2)
isqrtm_hmma_kernel(const float* __restrict__ x, float* __restrict__ out)
{
    extern __shared__ char smem[];
    const uint32_t sbase = smem_u32(smem);
    float* red = (float*)(smem + RED_OFF);

    const int tid = threadIdx.x;
    const int wid = tid >> 5, lane = tid & 31;
    const int wm = wid >> 1, wn = wid & 1;
    const int b = blockIdx.x;
    const float* X0 = x + (size_t)(2 * b) * 4096;
    const float* X1 = X0 + 4096;
    float* O0 = out + (size_t)(2 * b) * 4096;
    float* O1 = O0 + 4096;

    // ---- traces: warps 0,1 -> m0 diag; warps 2,3 -> m1 diag ----
    float tr = (tid < 64) ? __ldg(X0 + tid * 65) : __ldg(X1 + (tid - 64) * 65);
#pragma unroll
    for (int o = 16; o; o >>= 1) tr += __shfl_xor_sync(0xFFFFFFFFu, tr, o);
    if (lane == 0) red[wid] = tr;
    __syncthreads();
    const float normA0 = red[0] + red[1];
    const float normA1 = red[2] + red[3];
    const float inv0 = 1.0f / normA0, sq0 = sqrtf(normA0);
    const float inv1 = 1.0f / normA1, sq1 = sqrtf(normA1);
    __syncthreads();

    // ---- prologue per matrix: A -> bufs 4,5 ; Z = 1.5I - 0.5A -> bufs 2,3 ----
    {
        const int r  = tid >> 1;
        const int c0 = (tid & 1) * 32;
#pragma unroll 1
        for (int m = 0; m < 2; ++m) {
            const float* X = m ? X1 : X0;
            const float inv = m ? inv1 : inv0;
            char* base = smem + m * M1OFF;
#pragma unroll
            for (int q = 0; q < 16; ++q) {
                const int c = c0 + 2 * q;
                float2 f = *(const float2*)(X + r * 64 + c);
                float a0 = f.x * inv, a1 = f.y * inv;
                float z0 = (c     == r ? 1.5f : 0.0f) - 0.5f * a0;
                float z1 = (c + 1 == r ? 1.5f : 0.0f) - 0.5f * a1;
                __half p0, s0, p1, s1;
                uint32_t off = swz((uint32_t)(r * 128 + c * 2));
                split2(a0, p0, s0); split2(a1, p1, s1);
                *(uint32_t*)(base + 4 * BUF + off) = packh(p0, p1);
                *(uint32_t*)(base + 5 * BUF + off) = packh(s0, s1);
                split2(z0, p0, s0); split2(z1, p1, s1);
                *(uint32_t*)(base + 2 * BUF + off) = packh(p0, p1);
                *(uint32_t*)(base + 3 * BUF + off) = packh(s0, s1);
            }
        }
    }

    // ---- Newton-Schulz chain: 12 GEMM steps on both matrices ----
    // Y = A @ Z
    step2<0>(sbase, smem, 4*BUF, 5*BUF, 2*BUF, 3*BUF, 0*BUF, 1*BUF,
             O0, O1, 0.f, 0.f, wm, wn, lane);
#pragma unroll 1
    for (int it = 0; it < 3; ++it) {
        // T = 1.5I - 0.5 * Z@Y
        step2<1>(sbase, smem, 2*BUF, 3*BUF, 0*BUF, 1*BUF, 4*BUF, 5*BUF,
                 O0, O1, 0.f, 0.f, wm, wn, lane);
        // Y = Y @ T
        step2<0>(sbase, smem, 0*BUF, 1*BUF, 4*BUF, 5*BUF, 0*BUF, 1*BUF,
                 O0, O1, 0.f, 0.f, wm, wn, lane);
        // Z = T @ Z
        step2<0>(sbase, smem, 4*BUF, 5*BUF, 2*BUF, 3*BUF, 2*BUF, 3*BUF,
                 O0, O1, 0.f, 0.f, wm, wn, lane);
    }
    // T = 1.5I - 0.5 * Z@Y ; out = sqrt(normA) * (Y @ T)
    step2<1>(sbase, smem, 2*BUF, 3*BUF, 0*BUF, 1*BUF, 4*BUF, 5*BUF,
             O0, O1, 0.f, 0.f, wm, wn, lane);
    step2<2>(sbase, smem, 0*BUF, 1*BUF, 4*BUF, 5*BUF, 0, 0,
             O0, O1, sq0, sq1, wm, wn, lane);
}

extern "C" void kernel_launch(void* const* d_in, const int* in_sizes, int n_in,
                              void* d_out, int out_size)
{
    const float* x = (const float*)d_in[0];
    float* out = (float*)d_out;
    const int batches = in_sizes[0] / 4096;
    const int blocks = batches / 2;     // 2 matrices per CTA

    cudaFuncSetAttribute(isqrtm_hmma_kernel,
                         cudaFuncAttributeMaxDynamicSharedMemorySize, SMEM_TOTAL);
    isqrtm_hmma_kernel<<<blocks, NT, SMEM_TOTAL>>>(x, out);
}

// round 11
// speedup vs baseline: 1.0974x; 1.0568x over previous
#include <cuda_runtime.h>
#include <cuda_fp16.h>
#include <math.h>
#include <stdint.h>

#define NT 128
#define BUF 8192                       // one 64x64 fp16 buffer: 64 rows x 128B
#define SMEM_TOTAL (6*BUF + 64)
// buffer roles: 0,1 = Y splits ; 2,3 = Z splits ; 4,5 = T/A splits

__device__ __forceinline__ uint32_t swz(uint32_t b) { return b ^ ((b >> 3) & 0x70); }

__device__ __forceinline__ uint32_t smem_u32(const void* p) {
    uint32_t a;
    asm("{ .reg .u64 t; cvta.to.shared.u64 t, %1; cvt.u32.u64 %0, t; }" : "=r"(a) : "l"(p));
    return a;
}

__device__ __forceinline__ void ldsm4(uint32_t* r, uint32_t addr) {
    asm volatile("ldmatrix.sync.aligned.m8n8.x4.shared.b16 {%0,%1,%2,%3}, [%4];"
                 : "=r"(r[0]), "=r"(r[1]), "=r"(r[2]), "=r"(r[3]) : "r"(addr));
}

__device__ __forceinline__ void mma16816(float* c, const uint32_t* a,
                                         uint32_t b0, uint32_t b1) {
    asm volatile("mma.sync.aligned.m16n8k16.row.col.f32.f16.f16.f32 "
                 "{%0,%1,%2,%3}, {%4,%5,%6,%7}, {%8,%9}, {%0,%1,%2,%3};"
                 : "+f"(c[0]), "+f"(c[1]), "+f"(c[2]), "+f"(c[3])
                 : "r"(a[0]), "r"(a[1]), "r"(a[2]), "r"(a[3]), "r"(b0), "r"(b1));
}

// fp32 -> 2-term fp16 split
__device__ __forceinline__ void split2(float v, __half& h1, __half& h2) {
    h1 = __float2half_rn(v);
    h2 = __float2half_rn(v - __half2float(h1));
}
__device__ __forceinline__ uint32_t packh(__half a, __half b) {
    __half2 t; t.x = a; t.y = b;
    return *reinterpret_cast<uint32_t*>(&t);
}

// ---- load + MMA phase: acc = (a1+a2) @ (b1+b2), 3 partial products ----
// Both operands symmetric -> row.col is transpose-free. No barriers inside.
__device__ __forceinline__ void mma_phase(uint32_t sbase,
                                          int a1, int a2, int b1, int b2,
                                          int wm, int wn, int lane,
                                          float acc[2][4][4])
{
#pragma unroll
    for (int mt = 0; mt < 2; ++mt)
#pragma unroll
        for (int j = 0; j < 4; ++j)
#pragma unroll
            for (int q = 0; q < 4; ++q) acc[mt][j][q] = 0.0f;

    const int arow = wm * 32 + (lane & 15);
    const int acol = (lane >> 4) * 16;
    const int bl = lane & 7;
    const int bg = lane >> 3;
    const uint32_t bcol = (uint32_t)((bg >> 1) * 32 + (bg & 1) * 16);

#pragma unroll
    for (int ktp = 0; ktp < 2; ++ktp) {
        uint32_t A1[2][2][4], A2[2][2][4];
#pragma unroll
        for (int mt = 0; mt < 2; ++mt)
#pragma unroll
            for (int ktl = 0; ktl < 2; ++ktl) {
                uint32_t rel = swz((uint32_t)((arow + mt * 16) * 128 +
                                              ktp * 64 + ktl * 32 + acol));
                ldsm4(A1[mt][ktl], sbase + a1 + rel);
                ldsm4(A2[mt][ktl], sbase + a2 + rel);
            }
#pragma unroll
        for (int j = 0; j < 4; ++j) {
            const uint32_t rowb = (uint32_t)((wn * 32 + j * 8 + bl) * 128);
            uint32_t rel = swz(rowb + ktp * 64 + bcol);
            uint32_t Bx[4], Cx[4];
            ldsm4(Bx, sbase + b1 + rel);   // regs 0,1 = kt_lo ; 2,3 = kt_hi
            ldsm4(Cx, sbase + b2 + rel);
#pragma unroll
            for (int ktl = 0; ktl < 2; ++ktl) {
#pragma unroll
                for (int mt = 0; mt < 2; ++mt) {
                    mma16816(acc[mt][j], A1[mt][ktl], Bx[2*ktl], Bx[2*ktl+1]);
                    mma16816(acc[mt][j], A1[mt][ktl], Cx[2*ktl], Cx[2*ktl+1]);
                    mma16816(acc[mt][j], A2[mt][ktl], Bx[2*ktl], Bx[2*ktl+1]);
                }
            }
        }
    }
}

// ---- epilogue: transform, split, store. No barriers inside. ----
// MODE 0: dst = D   MODE 1: dst = 1.5I - 0.5 D   MODE 2: gmem O = scale*D
template <int MODE>
__device__ __forceinline__ void epi_phase(char* smem, int d1, int d2,
                                          float* __restrict__ O, float scale,
                                          int wm, int wn, int lane,
                                          const float acc[2][4][4])
{
    const int gr = lane >> 2, qp = lane & 3;
#pragma unroll
    for (int mt = 0; mt < 2; ++mt)
#pragma unroll
    for (int j = 0; j < 4; ++j) {
        const int colb = wn * 32 + j * 8 + 2 * qp;
#pragma unroll
        for (int half = 0; half < 2; ++half) {
            const int row = wm * 32 + mt * 16 + gr + half * 8;
            float v0 = acc[mt][j][half * 2 + 0];
            float v1 = acc[mt][j][half * 2 + 1];
            if (MODE == 1) {
                v0 = (colb     == row ? 1.5f : 0.0f) - 0.5f * v0;
                v1 = (colb + 1 == row ? 1.5f : 0.0f) - 0.5f * v1;
            }
            if (MODE == 2) {
                *(float2*)(O + row * 64 + colb) = make_float2(v0 * scale, v1 * scale);
            } else {
                __half p0, q0, p1, q1;
                split2(v0, p0, q0);
                split2(v1, p1, q1);
                uint32_t off = swz((uint32_t)(row * 128 + colb * 2));
                *(uint32_t*)(smem + d1 + off) = packh(p0, p1);
                *(uint32_t*)(smem + d2 + off) = packh(q0, q1);
            }
        }
    }
}

// single GEMM step: sync; mma; sync; epi
template <int MODE>
__device__ __forceinline__ void gemm_single(uint32_t sbase, char* smem,
                                            int a1, int a2, int b1, int b2,
                                            int d1, int d2,
                                            float* __restrict__ O, float scale,
                                            int wm, int wn, int lane)
{
    float acc[2][4][4];
    __syncthreads();
    mma_phase(sbase, a1, a2, b1, b2, wm, wn, lane, acc);
    __syncthreads();
    epi_phase<MODE>(smem, d1, d2, O, scale, wm, wn, lane, acc);
}

__global__ void __launch_bounds__(NT, 4)
isqrtm_hmma_kernel(const float* __restrict__ x, float* __restrict__ out)
{
    extern __shared__ char smem[];
    const uint32_t sbase = smem_u32(smem);
    float* red = (float*)(smem + 6 * BUF);

    const int tid = threadIdx.x;
    const int wid = tid >> 5, lane = tid & 31;
    const int wm = wid >> 1, wn = wid & 1;
    const int b = blockIdx.x;
    const float* X = x + (size_t)b * 4096;
    float* O = out + (size_t)b * 4096;

    // ---- trace(X) ----
    float tr = (tid < 64) ? __ldg(X + tid * 65) : 0.0f;
#pragma unroll
    for (int o = 16; o; o >>= 1) tr += __shfl_xor_sync(0xFFFFFFFFu, tr, o);
    if (lane == 0) red[wid] = tr;
    __syncthreads();
    const float normA = red[0] + red[1];
    const float inv = 1.0f / normA;
    const float sq  = sqrtf(normA);
    __syncthreads();

    // ---- prologue: A = X/normA -> bufs 4,5 ; Z = 1.5I - 0.5A -> bufs 2,3 ----
    {
        const int r  = tid >> 1;
        const int c0 = (tid & 1) * 32;
#pragma unroll
        for (int q = 0; q < 16; ++q) {
            const int c = c0 + 2 * q;
            float2 f = *(const float2*)(X + r * 64 + c);
            float a0 = f.x * inv, a1 = f.y * inv;
            float z0 = (c     == r ? 1.5f : 0.0f) - 0.5f * a0;
            float z1 = (c + 1 == r ? 1.5f : 0.0f) - 0.5f * a1;
            __half p0, s0, p1, s1;
            uint32_t off = swz((uint32_t)(r * 128 + c * 2));
            split2(a0, p0, s0); split2(a1, p1, s1);
            *(uint32_t*)(smem + 4 * BUF + off) = packh(p0, p1);
            *(uint32_t*)(smem + 5 * BUF + off) = packh(s0, s1);
            split2(z0, p0, s0); split2(z1, p1, s1);
            *(uint32_t*)(smem + 2 * BUF + off) = packh(p0, p1);
            *(uint32_t*)(smem + 3 * BUF + off) = packh(s0, s1);
        }
    }

    // ---- Newton-Schulz chain (12 GEMMs, 18 barriers) ----
    // Y = A @ Z
    gemm_single<0>(sbase, smem, 4*BUF, 5*BUF, 2*BUF, 3*BUF, 0*BUF, 1*BUF,
                   O, 0.f, wm, wn, lane);
#pragma unroll 1
    for (int it = 0; it < 3; ++it) {
        // T = 1.5I - 0.5 * Z@Y
        gemm_single<1>(sbase, smem, 2*BUF, 3*BUF, 0*BUF, 1*BUF, 4*BUF, 5*BUF,
                       O, 0.f, wm, wn, lane);
        // paired independent GEMMs: Y' = Y@T  ||  Z' = T@Z
        {
            float accY[2][4][4], accZ[2][4][4];
            __syncthreads();
            mma_phase(sbase, 0*BUF, 1*BUF, 4*BUF, 5*BUF, wm, wn, lane, accY);
            mma_phase(sbase, 4*BUF, 5*BUF, 2*BUF, 3*BUF, wm, wn, lane, accZ);
            __syncthreads();
            epi_phase<0>(smem, 0*BUF, 1*BUF, O, 0.f, wm, wn, lane, accY);
            epi_phase<0>(smem, 2*BUF, 3*BUF, O, 0.f, wm, wn, lane, accZ);
        }
    }
    // T = 1.5I - 0.5 * Z@Y ; out = sqrt(normA) * (Y @ T)
    gemm_single<1>(sbase, smem, 2*BUF, 3*BUF, 0*BUF, 1*BUF, 4*BUF, 5*BUF,
                   O, 0.f, wm, wn, lane);
    gemm_single<2>(sbase, smem, 0*BUF, 1*BUF, 4*BUF, 5*BUF, 0, 0,
                   O, sq, wm, wn, lane);
}

extern "C" void kernel_launch(void* const* d_in, const int* in_sizes, int n_in,
                              void* d_out, int out_size)
{
    const float* x = (const float*)d_in[0];
    float* out = (float*)d_out;
    const int batches = in_sizes[0] / 4096;

    cudaFuncSetAttribute(isqrtm_hmma_kernel,
                         cudaFuncAttributeMaxDynamicSharedMemorySize, SMEM_TOTAL);
    isqrtm_hmma_kernel<<<batches, NT, SMEM_TOTAL>>>(x, out);
}